// round 4
// baseline (speedup 1.0000x reference)
#include <cuda_runtime.h>

#define NIN   784
#define DD    10
#define WW    4
#define WD    40       // WW*DD
#define NOUT  10
#define NL    3        // N_LAYERS-1
#define TILE_B 256
#define KC    16
#define NCHUNK 49      // 784/16

// ---- dynamic smem layout (bytes) ----
// persistent weights:
#define SMEM_DW    0                      // data_w : 3*4*4*10*10 = 4800 f (19200 B)
#define SMEM_GW    19200                  // gate_w : 480 f (1920 B)
#define SMEM_DB    21120                  // data_b : 480 f (1920 B)
#define SMEM_WOUT  23040                  // W_out  : 400 f (1600 B)
#define SMEM_BIN   24640                  // b_in   : 40 f  (160 B)
// union region (phase-1 tiles alias phase-2 acts):
#define SMEM_XS    24800                  // xs  : float[KC*256]   (16384 B)
#define SMEM_WSD   (24800 + 16384)        // Wsd : float2[KC*WD]   (5120 B)
#define SMEM_ACTS  24800                  // acts: float[256*41]   (41984 B)
#define SMEM_TOTAL (24800 + 41984)        // 66784 B

__device__ __forceinline__ void ffma2(unsigned long long &d,
                                      unsigned long long a,
                                      unsigned long long b) {
    // packed f32x2 FMA: 2 FMAs per issue slot (3-reg scalar FFMA is half-rate on Blackwell)
    asm("fma.rn.f32x2 %0, %1, %2, %0;" : "+l"(d) : "l"(a), "l"(b));
}

extern __shared__ char smem_raw[];

__global__ void __launch_bounds__(256, 2)
routenet_kernel(const float* __restrict__ x,
                const float* __restrict__ Win,
                const float* __restrict__ bin,
                const float* __restrict__ gw,
                const float* __restrict__ dw,
                const float* __restrict__ db,
                const float* __restrict__ wout,
                float* __restrict__ out,
                int B)
{
    float*  dw_s   = (float*)(smem_raw + SMEM_DW);
    float*  gw_s   = (float*)(smem_raw + SMEM_GW);
    float*  db_s   = (float*)(smem_raw + SMEM_DB);
    float*  wout_s = (float*)(smem_raw + SMEM_WOUT);
    float*  bin_s  = (float*)(smem_raw + SMEM_BIN);
    float*  xs     = (float*)(smem_raw + SMEM_XS);
    float2* Wsd    = (float2*)(smem_raw + SMEM_WSD);
    float*  acts_s = (float*)(smem_raw + SMEM_ACTS);

    const int tid = threadIdx.x;
    const int block_row = blockIdx.x * TILE_B;

    // ---- load persistent (phase 2-4) weights once ----
    for (int i = tid; i < NL * WW * WW * DD * DD; i += 256) dw_s[i]   = dw[i];
    for (int i = tid; i < NL * WW * WW * DD;      i += 256) gw_s[i]   = gw[i];
    for (int i = tid; i < NL * WW * WW * DD;      i += 256) db_s[i]   = db[i];
    for (int i = tid; i < WW * NOUT * DD;         i += 256) wout_s[i] = wout[i];
    if (tid < WD) bin_s[tid] = bin[tid];

    // =====================================================================
    // Phase 1: acts0[256][40] = relu(x_tile @ Win^T + b_in)
    // thread tile: 8 batch rows (tb) x 5 outputs (td), f32x2-packed pairs
    // =====================================================================
    const int tb = tid & 31;   // batch group: rows tb*8 .. tb*8+7
    const int td = tid >> 5;   // output group: o = td*5 .. td*5+4

    unsigned long long acc[4][5];
    #pragma unroll
    for (int p = 0; p < 4; ++p)
        #pragma unroll
        for (int j = 0; j < 5; ++j) acc[p][j] = 0ull;

    const float* xrow = x + (size_t)(block_row + tid) * NIN;

    for (int c = 0; c < NCHUNK; ++c) {
        const int k0 = c * KC;
        __syncthreads();   // previous chunk's readers done before overwrite

        // x tile: thread loads 16 floats of its own row, stores transposed
        float4 v0 = *(const float4*)(xrow + k0);
        float4 v1 = *(const float4*)(xrow + k0 + 4);
        float4 v2 = *(const float4*)(xrow + k0 + 8);
        float4 v3 = *(const float4*)(xrow + k0 + 12);
        xs[ 0*256 + tid] = v0.x; xs[ 1*256 + tid] = v0.y;
        xs[ 2*256 + tid] = v0.z; xs[ 3*256 + tid] = v0.w;
        xs[ 4*256 + tid] = v1.x; xs[ 5*256 + tid] = v1.y;
        xs[ 6*256 + tid] = v1.z; xs[ 7*256 + tid] = v1.w;
        xs[ 8*256 + tid] = v2.x; xs[ 9*256 + tid] = v2.y;
        xs[10*256 + tid] = v2.z; xs[11*256 + tid] = v2.w;
        xs[12*256 + tid] = v3.x; xs[13*256 + tid] = v3.y;
        xs[14*256 + tid] = v3.z; xs[15*256 + tid] = v3.w;

        // W chunk, pre-duplicated into {w,w} pairs for f32x2
        for (int i = tid; i < KC * WD; i += 256) {
            int o  = i >> 4;          // 0..39
            int kk = i & 15;          // coalesced along k
            float w = Win[o * NIN + k0 + kk];
            Wsd[kk * WD + o] = make_float2(w, w);
        }
        __syncthreads();

        #pragma unroll
        for (int kk = 0; kk < KC; ++kk) {
            const ulonglong2* xp =
                (const ulonglong2*)(xs + kk * 256 + tb * 8);
            ulonglong2 xa = xp[0];
            ulonglong2 xb = xp[1];
            const unsigned long long* wp =
                (const unsigned long long*)Wsd + kk * WD + td * 5;
            #pragma unroll
            for (int j = 0; j < 5; ++j) {
                unsigned long long w2 = wp[j];
                ffma2(acc[0][j], xa.x, w2);
                ffma2(acc[1][j], xa.y, w2);
                ffma2(acc[2][j], xb.x, w2);
                ffma2(acc[3][j], xb.y, w2);
            }
        }
    }

    __syncthreads();   // all xs reads done; acts aliases xs region

    // bias + relu, transpose into acts_s[row][o] (stride 41: conflict-free)
    #pragma unroll
    for (int p = 0; p < 4; ++p) {
        #pragma unroll
        for (int j = 0; j < 5; ++j) {
            int o = td * 5 + j;
            float b  = bin_s[o];
            float lo = __uint_as_float((unsigned int)(acc[p][j] & 0xffffffffull));
            float hi = __uint_as_float((unsigned int)(acc[p][j] >> 32));
            acts_s[(tb * 8 + 2 * p    ) * 41 + o] = fmaxf(lo + b, 0.0f);
            acts_s[(tb * 8 + 2 * p + 1) * 41 + o] = fmaxf(hi + b, 0.0f);
        }
    }
    __syncthreads();

    // =====================================================================
    // Phases 2-4: one batch row per thread, acts in registers
    // =====================================================================
    float a[WW][DD];
    #pragma unroll
    for (int w = 0; w < WW; ++w)
        #pragma unroll
        for (int d = 0; d < DD; ++d)
            a[w][d] = acts_s[tid * 41 + w * DD + d];

    float tg = 0.0f;

    for (int l = 0; l < NL; ++l) {   // rolled: keeps I-footprint small
        const float* gwl = gw_s + l * (WW * WW * DD);
        const float* dwl = dw_s + l * (WW * WW * DD * DD);
        const float* dbl = db_s + l * (WW * WW * DD);

        float nxt[WW][DD];
        #pragma unroll
        for (int t = 0; t < WW; ++t)
            #pragma unroll
            for (int e = 0; e < DD; ++e) nxt[t][e] = 0.0f;

        #pragma unroll
        for (int s = 0; s < WW; ++s) {
            #pragma unroll
            for (int t = 0; t < WW; ++t) {
                const int   edge = s * WW + t;
                const float* gv  = gwl + edge * DD;
                float g = 0.0f;
                #pragma unroll
                for (int d = 0; d < DD; ++d) g += a[s][d] * gv[d];
                g = fminf(fmaxf(g, 0.0f), 1.0f);   // hardtanh(.,0,1)
                tg += g;

                const float* dm = dwl + edge * (DD * DD);
                const float* dv = dbl + edge * DD;
                #pragma unroll
                for (int e = 0; e < DD; ++e) {
                    float m = dv[e];
                    #pragma unroll
                    for (int din = 0; din < DD; ++din)
                        m += a[s][din] * dm[din * DD + e];
                    nxt[t][e] += g * m;
                }
            }
        }
        #pragma unroll
        for (int t = 0; t < WW; ++t)
            #pragma unroll
            for (int e = 0; e < DD; ++e)
                a[t][e] = fmaxf(nxt[t][e], 0.0f);
    }

    // ---- output banks + total_gate ----
    const size_t row = (size_t)block_row + tid;
    #pragma unroll
    for (int c = 0; c < NOUT; ++c) {
        float o = 0.0f;
        #pragma unroll
        for (int w = 0; w < WW; ++w)
            #pragma unroll
            for (int d = 0; d < DD; ++d)
                o += a[w][d] * wout_s[w * (NOUT * DD) + c * DD + d];
        out[row * NOUT + c] = o;
    }
    out[(size_t)B * NOUT + row] = tg;
}

extern "C" void kernel_launch(void* const* d_in, const int* in_sizes, int n_in,
                              void* d_out, int out_size)
{
    const float* x    = (const float*)d_in[0];
    const float* Win  = (const float*)d_in[1];
    const float* bin  = (const float*)d_in[2];
    const float* gw   = (const float*)d_in[3];
    const float* dw   = (const float*)d_in[4];
    const float* db   = (const float*)d_in[5];
    const float* wout = (const float*)d_in[6];

    const int B = in_sizes[0] / NIN;

    cudaFuncSetAttribute(routenet_kernel,
                         cudaFuncAttributeMaxDynamicSharedMemorySize,
                         SMEM_TOTAL);

    routenet_kernel<<<B / TILE_B, 256, SMEM_TOTAL>>>(
        x, Win, bin, gw, dw, db, wout, (float*)d_out, B);
}

// round 5
// speedup vs baseline: 1.2553x; 1.2553x over previous
#include <cuda_runtime.h>

typedef unsigned long long ull;

#define NIN   784
#define DD    10
#define WW    4
#define WD    40
#define NOUT  10
#define NL    3
#define KC    16
#define NCHUNK 49     // 784/16
#define TPB   256

__device__ __forceinline__ void ffma2(ull &d, ull a, ull b) {
    asm("fma.rn.f32x2 %0, %1, %2, %0;" : "+l"(d) : "l"(a), "l"(b));
}
__device__ __forceinline__ ull addf2(ull a, ull b) {
    ull r; asm("add.rn.f32x2 %0, %1, %2;" : "=l"(r) : "l"(a), "l"(b)); return r;
}
__device__ __forceinline__ ull pack2(float lo, float hi) {
    ull r; asm("mov.b64 %0, {%1, %2};" : "=l"(r) : "f"(lo), "f"(hi)); return r;
}
__device__ __forceinline__ void unpack2(ull v, float &lo, float &hi) {
    asm("mov.b64 {%0, %1}, %2;" : "=f"(lo), "=f"(hi) : "l"(v));
}

__global__ void __launch_bounds__(TPB, 2)
routenet_kernel(const float* __restrict__ x,
                const float* __restrict__ Win,
                const float* __restrict__ bin,
                const float* __restrict__ gw,
                const float* __restrict__ dw,
                const float* __restrict__ db,
                const float* __restrict__ wout,
                float* __restrict__ out,
                int B)
{
    // ---- static shared (31.2 KB total) ----
    __shared__ __align__(16) float ws[KC * WD];            // 2560 B, W chunk, k-major
    __shared__ __align__(16) float dwp[NL * 16 * DD * 12]; // data_w padded e->12 (23040 B)
    __shared__ __align__(16) float gws[NL * 16 * DD];      // 1920 B
    __shared__ __align__(16) float dbs[NL * 16 * DD];      // 1920 B
    __shared__ __align__(16) float wouts[WW * NOUT * DD];  // 1600 B
    __shared__ __align__(16) float bins[WD];               // 160 B

    const int tid = threadIdx.x;

    // ---- stage persistent weights (once per block) ----
    for (int i = tid; i < NL * 16 * DD * DD; i += TPB) {
        int e    = i % DD;
        int din  = (i / DD) % DD;
        int rest = i / (DD * DD);             // l*16 + edge
        dwp[(rest * DD + din) * 12 + e] = dw[i];
    }
    for (int i = tid; i < NL * 16 * DD; i += TPB) { gws[i] = gw[i]; dbs[i] = db[i]; }
    for (int i = tid; i < WW * NOUT * DD; i += TPB) wouts[i] = wout[i];
    if (tid < WD) bins[tid] = bin[tid];

    const int row = blockIdx.x * TPB + tid;
    const float* xrow = x + (size_t)row * NIN;

    // W-chunk staging indices (fixed per thread): 640 elems over 256 threads
    const int o0 = tid >> 4,          kk0 = tid & 15;
    const int o1 = (tid + 256) >> 4,  kk1 = (tid + 256) & 15;
    const int o2 = (tid + 512) >> 4,  kk2 = (tid + 512) & 15;   // only tid<128

    // ---- prologue: chunk 0 ----
    float w0 = Win[o0 * NIN + kk0];
    float w1 = Win[o1 * NIN + kk1];
    float w2 = (tid < 128) ? Win[o2 * NIN + kk2] : 0.0f;
    float4 xa0 = *(const float4*)(xrow +  0);
    float4 xa1 = *(const float4*)(xrow +  4);
    float4 xa2 = *(const float4*)(xrow +  8);
    float4 xa3 = *(const float4*)(xrow + 12);
    ws[kk0 * WD + o0] = w0;
    ws[kk1 * WD + o1] = w1;
    if (tid < 128) ws[kk2 * WD + o2] = w2;
    __syncthreads();

    ull acc[20];
    #pragma unroll
    for (int j = 0; j < 20; ++j) acc[j] = 0ull;

    // =====================================================================
    // Phase 1: acc[j] = {out_{2j}, out_{2j+1}} over k, x from registers,
    //          W broadcast from smem (10x LDS.128 per k per warp)
    // =====================================================================
    #pragma unroll 1
    for (int c = 0; c < NCHUNK; ++c) {
        float  wn0 = 0.f, wn1 = 0.f, wn2 = 0.f;
        float4 xn0, xn1, xn2, xn3;
        if (c + 1 < NCHUNK) {
            const int kb = (c + 1) * KC;
            wn0 = Win[o0 * NIN + kb + kk0];
            wn1 = Win[o1 * NIN + kb + kk1];
            if (tid < 128) wn2 = Win[o2 * NIN + kb + kk2];
            xn0 = *(const float4*)(xrow + kb);
            xn1 = *(const float4*)(xrow + kb + 4);
            xn2 = *(const float4*)(xrow + kb + 8);
            xn3 = *(const float4*)(xrow + kb + 12);
        }

        #pragma unroll
        for (int q = 0; q < 4; ++q) {
            float4 xq = (q == 0) ? xa0 : (q == 1) ? xa1 : (q == 2) ? xa2 : xa3;
            float xs4[4] = {xq.x, xq.y, xq.z, xq.w};
            #pragma unroll
            for (int r = 0; r < 4; ++r) {
                const int kk = q * 4 + r;
                ull x2 = pack2(xs4[r], xs4[r]);
                const ulonglong2* wp = (const ulonglong2*)(ws + kk * WD);
                #pragma unroll
                for (int j = 0; j < 10; ++j) {
                    ulonglong2 wv = wp[j];     // broadcast LDS.128: {w4j,w4j+1},{w4j+2,w4j+3}
                    ffma2(acc[2 * j],     x2, wv.x);
                    ffma2(acc[2 * j + 1], x2, wv.y);
                }
            }
        }

        __syncthreads();                     // readers done with chunk c
        if (c + 1 < NCHUNK) {
            ws[kk0 * WD + o0] = wn0;
            ws[kk1 * WD + o1] = wn1;
            if (tid < 128) ws[kk2 * WD + o2] = wn2;
            xa0 = xn0; xa1 = xn1; xa2 = xn2; xa3 = xn3;
        }
        __syncthreads();                     // chunk c+1 visible
    }

    // bias + relu -> a[4][10] (all in registers)
    float a[WW][DD];
    {
        const ull* b2 = (const ull*)bins;
        #pragma unroll
        for (int j = 0; j < 20; ++j) {
            ull v = addf2(acc[j], b2[j]);
            float lo, hi; unpack2(v, lo, hi);
            const int o = 2 * j;
            a[o / DD][o % DD]             = fmaxf(lo, 0.0f);
            a[(o + 1) / DD][(o + 1) % DD] = fmaxf(hi, 0.0f);
        }
    }

    // =====================================================================
    // Phases 2-4: routed layers, f32x2 over e-dimension
    // =====================================================================
    float tg = 0.0f;

    #pragma unroll 1
    for (int l = 0; l < NL; ++l) {
        const float* gwl = gws + l * 160;
        const float* dbl = dbs + l * 160;
        const float* dwl = dwp + l * 16 * 120;

        ull nxt[WW][5];
        #pragma unroll
        for (int t = 0; t < WW; ++t)
            #pragma unroll
            for (int j = 0; j < 5; ++j) nxt[t][j] = 0ull;

        #pragma unroll
        for (int s = 0; s < WW; ++s) {
            ull a2[DD];
            #pragma unroll
            for (int d = 0; d < DD; ++d) a2[d] = pack2(a[s][d], a[s][d]);

            #pragma unroll
            for (int t = 0; t < WW; ++t) {
                const int edge = s * WW + t;

                // gate (scalar dot, broadcast smem)
                const float* gv = gwl + edge * DD;
                float g = 0.0f;
                #pragma unroll
                for (int d = 0; d < DD; ++d) g += a[s][d] * gv[d];
                g = fminf(fmaxf(g, 0.0f), 1.0f);
                tg += g;
                ull g2 = pack2(g, g);

                // message m = data_b + a[s] @ data_w   (f32x2 over e)
                ull m[5];
                const ull* bv = (const ull*)(dbl + edge * DD);   // 8B-aligned
                #pragma unroll
                for (int j = 0; j < 5; ++j) m[j] = bv[j];

                const float* drow = dwl + edge * 120;            // 16B-aligned rows (stride 48B)
                #pragma unroll
                for (int din = 0; din < DD; ++din) {
                    const char* rp = (const char*)(drow + din * 12);
                    ulonglong2 wA = *(const ulonglong2*)rp;        // e0..e3
                    ulonglong2 wB = *(const ulonglong2*)(rp + 16); // e4..e7
                    ull        wC = *(const ull*)(rp + 32);        // e8,e9
                    ull ad = a2[din];
                    ffma2(m[0], ad, wA.x);
                    ffma2(m[1], ad, wA.y);
                    ffma2(m[2], ad, wB.x);
                    ffma2(m[3], ad, wB.y);
                    ffma2(m[4], ad, wC);
                }

                #pragma unroll
                for (int j = 0; j < 5; ++j) ffma2(nxt[t][j], g2, m[j]);
            }
        }

        #pragma unroll
        for (int t = 0; t < WW; ++t)
            #pragma unroll
            for (int j = 0; j < 5; ++j) {
                float lo, hi; unpack2(nxt[t][j], lo, hi);
                a[t][2 * j]     = fmaxf(lo, 0.0f);
                a[t][2 * j + 1] = fmaxf(hi, 0.0f);
            }
    }

    // ---- output banks + total_gate ----
    float ov[NOUT];
    #pragma unroll
    for (int c = 0; c < NOUT; ++c) {
        float o = 0.0f;
        #pragma unroll
        for (int w = 0; w < WW; ++w)
            #pragma unroll
            for (int d = 0; d < DD; ++d)
                o += a[w][d] * wouts[(w * NOUT + c) * DD + d];
        ov[c] = o;
    }
    float2* op = (float2*)(out + (size_t)row * NOUT);
    #pragma unroll
    for (int j = 0; j < 5; ++j) op[j] = make_float2(ov[2 * j], ov[2 * j + 1]);
    out[(size_t)B * NOUT + row] = tg;
}

extern "C" void kernel_launch(void* const* d_in, const int* in_sizes, int n_in,
                              void* d_out, int out_size)
{
    const float* x    = (const float*)d_in[0];
    const float* Win  = (const float*)d_in[1];
    const float* bin  = (const float*)d_in[2];
    const float* gw   = (const float*)d_in[3];
    const float* dw   = (const float*)d_in[4];
    const float* db   = (const float*)d_in[5];
    const float* wout = (const float*)d_in[6];

    const int B = in_sizes[0] / NIN;

    routenet_kernel<<<B / TPB, TPB>>>(x, Win, bin, gw, dw, db, wout,
                                      (float*)d_out, B);
}

// round 6
// speedup vs baseline: 1.3907x; 1.1079x over previous
#include <cuda_runtime.h>

typedef unsigned long long ull;

#define NIN   784
#define DD    10
#define WW    4
#define NOUT  10
#define NL    3
#define TPB   256

// __device__ scratch (allowed; no allocation)
__device__ float Wt_g[NIN * 64];             // k-major Win, 8-padded per 5-output group
__device__ float dwp_g[NL * 16 * DD * 12];   // data_w, e padded 10->12 (48B rows)

__global__ void prep_kernel(const float* __restrict__ Win,
                            const float* __restrict__ dw)
{
    int i = blockIdx.x * blockDim.x + threadIdx.x;
    if (i < NIN * 64) {
        int k = i >> 6, c = i & 63;
        int og = c >> 3, j = c & 7;          // slot j in og's 8-wide slice
        float v = 0.0f;
        if (j < 5) v = Win[(og * 5 + j) * NIN + k];
        Wt_g[i] = v;
    }
    if (i < NL * 16 * DD * 12) {
        int e = i % 12;
        int r = i / 12;                      // (l*16+edge)*10 + din
        float v = 0.0f;
        if (e < DD) v = dw[r * DD + e];
        dwp_g[i] = v;
    }
}

__device__ __forceinline__ void ffma2(ull &d, ull a, ull b) {
    asm("fma.rn.f32x2 %0, %1, %2, %0;" : "+l"(d) : "l"(a), "l"(b));
}
__device__ __forceinline__ ull pack2(float lo, float hi) {
    ull r; asm("mov.b64 %0, {%1, %2};" : "=l"(r) : "f"(lo), "f"(hi)); return r;
}
__device__ __forceinline__ void unpack2(ull v, float &lo, float &hi) {
    asm("mov.b64 {%0, %1}, %2;" : "=f"(lo), "=f"(hi) : "l"(v));
}

__global__ void __launch_bounds__(TPB, 2)
routenet_kernel(const float* __restrict__ x,
                const float* __restrict__ bin,
                const float* __restrict__ gw,
                const float* __restrict__ db,
                const float* __restrict__ wout,
                float* __restrict__ out,
                int B)
{
    __shared__ __align__(16) float gws[NL * 16 * DD];    // 1920 B
    __shared__ __align__(16) float dbs[NL * 16 * DD];    // 1920 B
    __shared__ __align__(16) float wouts[WW * NOUT * DD];// 1600 B
    __shared__ __align__(16) float bins[40];             // 160 B
    __shared__ __align__(16) float acts[TPB * 41];       // 41984 B  (total 47.6 KB)

    const int tid = threadIdx.x;

    for (int i = tid; i < NL * 16 * DD; i += TPB) { gws[i] = gw[i]; dbs[i] = db[i]; }
    for (int i = tid; i < WW * NOUT * DD; i += TPB) wouts[i] = wout[i];
    if (tid < 40) bins[tid] = bin[tid];
    __syncthreads();

    // =====================================================================
    // Phase 1: thread = (rowgroup rg: 8 rows) x (outgroup og: 5 outputs)
    // warp = 4 rowgroups x 8 outgroups; x lanes dedup via same-line LDG.
    // =====================================================================
    const int og = tid & 7;       // outputs og*5 .. og*5+4
    const int rg = tid >> 3;      // rows rg*8 .. rg*8+7 within block
    const int row0 = blockIdx.x * TPB + rg * 8;
    const float* xr = x + (size_t)row0 * NIN;
    const float* wb = Wt_g + og * 8;

    ull acc[4][5];
    #pragma unroll
    for (int p = 0; p < 4; ++p)
        #pragma unroll
        for (int j = 0; j < 5; ++j) acc[p][j] = 0ull;

    #pragma unroll 1
    for (int c = 0; c < NIN / 4; ++c) {
        // 8 rows x 4 k-values of x  (8 LDG.128, 4 lines each, og-lanes dedup)
        float xs[8][4];
        #pragma unroll
        for (int r = 0; r < 8; ++r) {
            float4 t = __ldg((const float4*)(xr + r * NIN + c * 4));
            xs[r][0] = t.x; xs[r][1] = t.y; xs[r][2] = t.z; xs[r][3] = t.w;
        }
        #pragma unroll
        for (int kk = 0; kk < 4; ++kk) {
            const float* wrow = wb + (c * 4 + kk) * 64;
            float4 wa = __ldg((const float4*)wrow);      // w0..w3 (uniform per og)
            float  w4 = __ldg(wrow + 4);                 // w4
            float wv[5] = {wa.x, wa.y, wa.z, wa.w, w4};

            ull xp[4];
            #pragma unroll
            for (int p = 0; p < 4; ++p)
                xp[p] = pack2(xs[2 * p][kk], xs[2 * p + 1][kk]);

            #pragma unroll
            for (int j = 0; j < 5; ++j) {
                ull wd = pack2(wv[j], wv[j]);
                ffma2(acc[0][j], xp[0], wd);
                ffma2(acc[1][j], xp[1], wd);
                ffma2(acc[2][j], xp[2], wd);
                ffma2(acc[3][j], xp[3], wd);
            }
        }
    }

    // bias + relu -> acts smem (store banks (8rg+5og) mod 32: all distinct)
    #pragma unroll
    for (int p = 0; p < 4; ++p)
        #pragma unroll
        for (int j = 0; j < 5; ++j) {
            int o = og * 5 + j;
            float b = bins[o];
            float lo, hi; unpack2(acc[p][j], lo, hi);
            acts[(rg * 8 + 2 * p)     * 41 + o] = fmaxf(lo + b, 0.0f);
            acts[(rg * 8 + 2 * p + 1) * 41 + o] = fmaxf(hi + b, 0.0f);
        }
    __syncthreads();

    // =====================================================================
    // Phases 2-4: one row per thread; data_w via uniform LDG (line-dedup'd)
    // =====================================================================
    float a[WW][DD];
    #pragma unroll
    for (int w = 0; w < WW; ++w)
        #pragma unroll
        for (int d = 0; d < DD; ++d)
            a[w][d] = acts[tid * 41 + w * DD + d];

    float tg = 0.0f;

    #pragma unroll 1
    for (int l = 0; l < NL; ++l) {
        const float* gwl = gws + l * 160;
        const float* dbl = dbs + l * 160;
        const float* dwl = dwp_g + l * 16 * 120;

        ull nxt[WW][5];
        #pragma unroll
        for (int t = 0; t < WW; ++t)
            #pragma unroll
            for (int j = 0; j < 5; ++j) nxt[t][j] = 0ull;

        #pragma unroll
        for (int s = 0; s < WW; ++s) {
            ull a2[DD];
            #pragma unroll
            for (int d = 0; d < DD; ++d) a2[d] = pack2(a[s][d], a[s][d]);

            #pragma unroll
            for (int t = 0; t < WW; ++t) {
                const int edge = s * WW + t;

                const float* gv = gwl + edge * DD;
                float g = 0.0f;
                #pragma unroll
                for (int d = 0; d < DD; ++d) g += a[s][d] * gv[d];
                g = fminf(fmaxf(g, 0.0f), 1.0f);
                tg += g;
                ull g2 = pack2(g, g);

                ull m[5];
                const ull* bv = (const ull*)(dbl + edge * DD);
                #pragma unroll
                for (int j = 0; j < 5; ++j) m[j] = bv[j];

                const float* drow = dwl + edge * 120;    // 48B rows, 16B aligned
                #pragma unroll
                for (int din = 0; din < DD; ++din) {
                    const char* rp = (const char*)(drow + din * 12);
                    ulonglong2 wA = __ldg((const ulonglong2*)rp);        // e0..e3
                    ulonglong2 wB = __ldg((const ulonglong2*)(rp + 16)); // e4..e7
                    ull        wC = __ldg((const ull*)(rp + 32));        // e8,e9
                    ull ad = a2[din];
                    ffma2(m[0], ad, wA.x);
                    ffma2(m[1], ad, wA.y);
                    ffma2(m[2], ad, wB.x);
                    ffma2(m[3], ad, wB.y);
                    ffma2(m[4], ad, wC);
                }

                #pragma unroll
                for (int j = 0; j < 5; ++j) ffma2(nxt[t][j], g2, m[j]);
            }
        }

        #pragma unroll
        for (int t = 0; t < WW; ++t)
            #pragma unroll
            for (int j = 0; j < 5; ++j) {
                float lo, hi; unpack2(nxt[t][j], lo, hi);
                a[t][2 * j]     = fmaxf(lo, 0.0f);
                a[t][2 * j + 1] = fmaxf(hi, 0.0f);
            }
    }

    // ---- output banks + total_gate ----
    const size_t row = (size_t)blockIdx.x * TPB + tid;
    float ov[NOUT];
    #pragma unroll
    for (int c = 0; c < NOUT; ++c) {
        float o = 0.0f;
        #pragma unroll
        for (int w = 0; w < WW; ++w)
            #pragma unroll
            for (int d = 0; d < DD; ++d)
                o += a[w][d] * wouts[(w * NOUT + c) * DD + d];
        ov[c] = o;
    }
    float2* op = (float2*)(out + row * NOUT);
    #pragma unroll
    for (int j = 0; j < 5; ++j) op[j] = make_float2(ov[2 * j], ov[2 * j + 1]);
    out[(size_t)B * NOUT + row] = tg;
}

extern "C" void kernel_launch(void* const* d_in, const int* in_sizes, int n_in,
                              void* d_out, int out_size)
{
    const float* x    = (const float*)d_in[0];
    const float* Win  = (const float*)d_in[1];
    const float* bin  = (const float*)d_in[2];
    const float* gw   = (const float*)d_in[3];
    const float* dw   = (const float*)d_in[4];
    const float* db   = (const float*)d_in[5];
    const float* wout = (const float*)d_in[6];

    const int B = in_sizes[0] / NIN;

    prep_kernel<<<(NIN * 64 + TPB - 1) / TPB, TPB>>>(Win, dw);
    routenet_kernel<<<B / TPB, TPB>>>(x, bin, gw, db, wout, (float*)d_out, B);
}